// round 12
// baseline (speedup 1.0000x reference)
#include <cuda_runtime.h>
#include <math.h>
#include <stdint.h>

#define NTOK 4096
#define DIM  1024
#define FF   4096
#define NEXP 32
#define TOPK 2
#define CAP  512

__device__ float g_xr [(size_t)NTOK * DIM];        // 16 MB: x pre-rounded to tf32
__device__ float g_h  [(size_t)NEXP * CAP * FF];   // 256 MB: gelu(fc1), rounded, k-major
__device__ float g_yo [(size_t)NEXP * CAP * DIM];  // 64 MB
__device__ int   g_slot_token[NEXP * CAP];
__device__ int   g_pair_slot[NTOK * TOPK];
__device__ float g_pair_w[NTOK * TOPK];
__device__ int   g_topi[NTOK * TOPK];
__device__ int   g_nused[NEXP];

// ---------------- helpers ----------------
__device__ __forceinline__ uint32_t smem_u32(const void* p) {
    uint32_t a;
    asm("{ .reg .u64 t; cvta.to.shared.u64 t, %1; cvt.u32.u64 %0, t; }" : "=r"(a) : "l"(p));
    return a;
}
__device__ __forceinline__ void cp16(uint32_t d, const void* s) {
    asm volatile("cp.async.cg.shared.global [%0], [%1], 16;" :: "r"(d), "l"(s));
}
__device__ __forceinline__ void cp_commit() { asm volatile("cp.async.commit_group;"); }
template <int N>
__device__ __forceinline__ void cp_wait() { asm volatile("cp.async.wait_group %0;" :: "n"(N)); }

__device__ __forceinline__ void sts_f32(uint32_t addr, float v) {
    asm volatile("st.shared.f32 [%0], %1;" :: "r"(addr), "f"(v));
}
__device__ __forceinline__ void ldsm_x4(uint32_t& r0, uint32_t& r1, uint32_t& r2, uint32_t& r3,
                                        uint32_t addr) {
    asm volatile("ldmatrix.sync.aligned.m8n8.x4.shared.b16 {%0,%1,%2,%3}, [%4];"
                 : "=r"(r0), "=r"(r1), "=r"(r2), "=r"(r3) : "r"(addr));
}
__device__ __forceinline__ void ldsm_x2(uint32_t& r0, uint32_t& r1, uint32_t addr) {
    asm volatile("ldmatrix.sync.aligned.m8n8.x2.shared.b16 {%0,%1}, [%2];"
                 : "=r"(r0), "=r"(r1) : "r"(addr));
}
__device__ __forceinline__ uint32_t f2tf(uint32_t x) {
    uint32_t r;
    asm("cvt.rna.tf32.f32 %0, %1;" : "=r"(r) : "f"(__uint_as_float(x)));
    return r;
}
__device__ __forceinline__ float f2tf_f(float x) {
    uint32_t r;
    asm("cvt.rna.tf32.f32 %0, %1;" : "=r"(r) : "f"(x));
    return __uint_as_float(r);
}
__device__ __forceinline__ void mma_tf32(float* c, uint32_t a0, uint32_t a1, uint32_t a2,
                                         uint32_t a3, uint32_t b0, uint32_t b1) {
    asm volatile(
        "mma.sync.aligned.m16n8k8.row.col.f32.tf32.tf32.f32 "
        "{%0,%1,%2,%3}, {%4,%5,%6,%7}, {%8,%9}, {%0,%1,%2,%3};"
        : "+f"(c[0]), "+f"(c[1]), "+f"(c[2]), "+f"(c[3])
        : "r"(a0), "r"(a1), "r"(a2), "r"(a3), "r"(b0), "r"(b1));
}
__device__ __forceinline__ float gelu_tanh(float v) {
    float c = v + 0.044715f * v * v * v;
    return 0.5f * v * (1.0f + tanhf(0.7978845608028654f * c));
}

#define ROWB   80          // smem row stride: 64B (16 fp32 = K16) + 16B pad
#define TILEB  (128 * ROWB)
#define STAGES 4
#define SMEMB1 (2 * STAGES * TILEB + 512)         // gemm1: A+B 4-stage + tok
#define SMEMB2 (STAGES * TILEB + 2 * TILEB + 512) // gemm2: A 4-stage + B double buf

// ---------------- pre-round x: fp32 -> tf32(RNA) bits ----------------------
__global__ __launch_bounds__(256) void roundx_kernel(const float* __restrict__ src,
                                                     float* __restrict__ dst) {
    int i = blockIdx.x * 256 + threadIdx.x;
    const float4* s = (const float4*)src;
    float4* d = (float4*)dst;
    float4 v = s[i];
    d[i] = make_float4(f2tf_f(v.x), f2tf_f(v.y), f2tf_f(v.z), f2tf_f(v.w));
}

// ---------------- gating ----------------
__global__ void gate_kernel(const float* __restrict__ x, const float* __restrict__ gw,
                            const float* __restrict__ gb) {
    int warp = (blockIdx.x * blockDim.x + threadIdx.x) >> 5;
    int lane = threadIdx.x & 31;
    if (warp >= NTOK) return;
    const float4* xr = (const float4*)(x + (size_t)warp * DIM);
    float4 xv[8];
#pragma unroll
    for (int j = 0; j < 8; j++) xv[j] = xr[j * 32 + lane];
    float mylogit = 0.0f;
    for (int e = 0; e < NEXP; e++) {
        const float4* wr = (const float4*)(gw + (size_t)e * DIM);
        float s = 0.0f;
#pragma unroll
        for (int j = 0; j < 8; j++) {
            float4 wv = wr[j * 32 + lane];
            s += xv[j].x * wv.x + xv[j].y * wv.y + xv[j].z * wv.z + xv[j].w * wv.w;
        }
#pragma unroll
        for (int o = 16; o > 0; o >>= 1) s += __shfl_xor_sync(0xffffffffu, s, o);
        if (lane == e) mylogit = s + gb[e];
    }
    float m0 = mylogit; int i0 = lane;
#pragma unroll
    for (int o = 16; o > 0; o >>= 1) {
        float ov = __shfl_xor_sync(0xffffffffu, m0, o);
        int   oi = __shfl_xor_sync(0xffffffffu, i0, o);
        if (ov > m0 || (ov == m0 && oi < i0)) { m0 = ov; i0 = oi; }
    }
    float v2 = (lane == i0) ? -INFINITY : mylogit;
    float m1 = v2; int i1 = lane;
#pragma unroll
    for (int o = 16; o > 0; o >>= 1) {
        float ov = __shfl_xor_sync(0xffffffffu, m1, o);
        int   oi = __shfl_xor_sync(0xffffffffu, i1, o);
        if (ov > m1 || (ov == m1 && oi < i1)) { m1 = ov; i1 = oi; }
    }
    if (lane == 0) {
        float w0 = 1.0f / (1.0f + expf(m1 - m0));
        g_topi[warp * 2 + 0] = i0;
        g_topi[warp * 2 + 1] = i1;
        g_pair_w[warp * 2 + 0] = w0;
        g_pair_w[warp * 2 + 1] = 1.0f - w0;
    }
}

// ---------------- ordered capacity scan ----------------
__global__ void scan_kernel() {
    int lane = threadIdx.x;
    int cnt = 0;
    for (int base = 0; base < NTOK * TOPK; base += 32) {
        int v = g_topi[base + lane];
#pragma unroll
        for (int j = 0; j < 32; j++) {
            int ev = __shfl_sync(0xffffffffu, v, j);
            if (ev == lane) {
                int pos = cnt++;
                int i = base + j;
                if (pos < CAP) {
                    g_pair_slot[i] = lane * CAP + pos;
                    g_slot_token[lane * CAP + pos] = i >> 1;
                } else {
                    g_pair_slot[i] = -1;
                }
            }
        }
    }
    g_nused[lane] = min(cnt, CAP);
}

// ---------------- tf32 compute cores: warp tile 64x32, K=16 per iter -------
template <int CVTB>
__device__ __forceinline__ void compute_iter(uint32_t sA, uint32_t sB, int m0, int n0, int lane,
                                             float acc[4][4][4]) {
    uint32_t b[4][2][2];
    const uint32_t brow = (uint32_t)(n0 + (lane & 7)) * ROWB + (((lane >> 3) & 1) * 16);
#pragma unroll
    for (int nj = 0; nj < 4; nj++) {
        uint32_t ba = sB + brow + nj * 8 * ROWB;
        ldsm_x2(b[nj][0][0], b[nj][0][1], ba);        // k0-7
        ldsm_x2(b[nj][1][0], b[nj][1][1], ba + 32);   // k8-15
    }
    if (CVTB) {
#pragma unroll
        for (int nj = 0; nj < 4; nj++)
#pragma unroll
            for (int ks = 0; ks < 2; ks++) {
                b[nj][ks][0] = f2tf(b[nj][ks][0]);
                b[nj][ks][1] = f2tf(b[nj][ks][1]);
            }
    }
    const uint32_t arow = (uint32_t)(m0 + (lane & 15)) * ROWB + ((lane >> 4) * 16);
#pragma unroll
    for (int mi = 0; mi < 4; mi++) {
        uint32_t a0[4], a1[4];
        uint32_t aa = sA + arow + mi * 16 * ROWB;
        ldsm_x4(a0[0], a0[1], a0[2], a0[3], aa);        // k0-7
        ldsm_x4(a1[0], a1[1], a1[2], a1[3], aa + 32);   // k8-15
#pragma unroll
        for (int nj = 0; nj < 4; nj++)
            mma_tf32(acc[mi][nj], a0[0], a0[1], a0[2], a0[3], b[nj][0][0], b[nj][0][1]);
#pragma unroll
        for (int nj = 0; nj < 4; nj++)
            mma_tf32(acc[mi][nj], a1[0], a1[1], a1[2], a1[3], b[nj][1][0], b[nj][1][1]);
    }
}

__device__ __forceinline__ void fill_stage(uint32_t dA, uint32_t dB, const char* sa,
                                           const char* sb) {
    cp16(dA, sa); cp16(dA + 16, sa + 16);
    cp16(dB, sb); cp16(dB + 16, sb + 16);
}

// ---------------- GEMM1: h = gelu(gather(xr) @ w1^T + b1) ----------------
__global__ __launch_bounds__(256, 2) void gemm1_kernel(const float* __restrict__ w1,
                                                       const float* __restrict__ b1) {
    const int e = blockIdx.z;
    const int nu = g_nused[e];
    const int row0 = blockIdx.y * 128;
    if (row0 >= nu) return;
    const int col0 = blockIdx.x * 128;

    extern __shared__ __align__(16) char smem[];
    int* tok = (int*)(smem + 2 * STAGES * TILEB);
    const int tid = threadIdx.x;
    const int lane = tid & 31, wid = tid >> 5;
    const int m0 = (wid & 1) * 64, n0 = (wid >> 1) * 32;

    if (tid < 128) {
        int c = row0 + tid;
        tok[tid] = (c < nu) ? g_slot_token[e * CAP + c] : 0;
    }
    __syncthreads();

    const uint32_t sA0 = smem_u32(smem), sB0 = sA0 + STAGES * TILEB;
    const int r = tid >> 1, half = tid & 1;
    const char* asrc = (const char*)(g_xr + (size_t)tok[r] * DIM) + half * 32;
    const char* bsrc = (const char*)(w1 + ((size_t)e * FF + col0 + r) * DIM) + half * 32;
    const uint32_t dA = sA0 + r * ROWB + half * 32;
    const uint32_t dB = sB0 + r * ROWB + half * 32;

    float acc[4][4][4];
#pragma unroll
    for (int i = 0; i < 4; i++)
#pragma unroll
        for (int j = 0; j < 4; j++)
#pragma unroll
            for (int q = 0; q < 4; q++) acc[i][j][q] = 0.0f;

    const int NIT = DIM / 16;
#pragma unroll
    for (int s = 0; s < STAGES - 1; s++) {
        fill_stage(dA + s * TILEB, dB + s * TILEB, asrc + s * 64, bsrc + s * 64);
        cp_commit();
    }
    for (int it = 0; it < NIT; ++it) {
        cp_wait<STAGES - 2>();
        __syncthreads();
        const int pf = it + STAGES - 1;
        if (pf < NIT) {
            const int ps = pf & (STAGES - 1);
            fill_stage(dA + ps * TILEB, dB + ps * TILEB, asrc + (size_t)pf * 64,
                       bsrc + (size_t)pf * 64);
        }
        cp_commit();
        const int s = it & (STAGES - 1);
        compute_iter<1>(sA0 + s * TILEB, sB0 + s * TILEB, m0, n0, lane, acc);
    }

    // epilogue: bias + gelu, rounded to tf32 -> g_h (k-major for GEMM2)
    const int rbase = lane >> 2, cbase = (lane & 3) * 2;
#pragma unroll
    for (int mi = 0; mi < 4; mi++) {
#pragma unroll
        for (int nj = 0; nj < 4; nj++) {
#pragma unroll
            for (int hrow = 0; hrow < 2; hrow++) {
                int rl = m0 + mi * 16 + rbase + hrow * 8;
                int f = col0 + n0 + nj * 8 + cbase;
                float v0 = acc[mi][nj][hrow * 2 + 0] + b1[e * FF + f];
                float v1 = acc[mi][nj][hrow * 2 + 1] + b1[e * FF + f + 1];
                v0 = f2tf_f(gelu_tanh(v0)); v1 = f2tf_f(gelu_tanh(v1));
                float* hr = g_h + (size_t)(e * CAP + row0 + rl) * FF + f;
                *(float2*)hr = make_float2(v0, v1);
            }
        }
    }
}

// ---------------- GEMM2: yo = h @ w2[e]^(T in smem) + b2 -------------------
// A (g_h) via cp.async 4-stage; B (native w2) via LDG-prefetch + transposed
// st.shared into a double-buffered [n][k] tile, tf32-rounded in flight.
__global__ __launch_bounds__(256, 2) void gemm2_kernel(const float* __restrict__ w2,
                                                       const float* __restrict__ b2) {
    const int e = blockIdx.z;
    const int nu = g_nused[e];
    const int row0 = blockIdx.y * 128;
    if (row0 >= nu) return;
    const int col0 = blockIdx.x * 128;

    extern __shared__ __align__(16) char smem[];
    const int tid = threadIdx.x;
    const int lane = tid & 31, wid = tid >> 5;
    const int m0 = (wid & 1) * 64, n0 = (wid >> 1) * 32;

    const uint32_t sA0 = smem_u32(smem);
    const uint32_t sB0 = sA0 + STAGES * TILEB;     // two B buffers follow A stages
    const int r = tid >> 1, half = tid & 1;
    const char* asrc = (const char*)(g_h + (size_t)(e * CAP + row0 + r) * FF) + half * 32;
    const uint32_t dA = sA0 + r * ROWB + half * 32;

    // B transpose-fill mapping: warp covers one k row pair {kk, kk+8}
    const int kk = tid >> 5;            // 0..7
    const int cg = (tid & 31) * 4;      // n column group 0..124
    const float* bbase = w2 + (size_t)e * FF * DIM + col0 + cg + (size_t)kk * DIM;
    const uint32_t sBt = sB0 + (uint32_t)cg * ROWB + kk * 4;  // +j*ROWB per n; +32 for kk+8

    float acc[4][4][4];
#pragma unroll
    for (int i = 0; i < 4; i++)
#pragma unroll
        for (int j = 0; j < 4; j++)
#pragma unroll
            for (int q = 0; q < 4; q++) acc[i][j][q] = 0.0f;

    const int NIT = FF / 16;

    // A prologue (stages 0..2)
#pragma unroll
    for (int s = 0; s < STAGES - 1; s++) {
        cp16(dA + s * TILEB, asrc + s * 64);
        cp16(dA + s * TILEB + 16, asrc + s * 64 + 16);
        cp_commit();
    }
    // B prologue: ldg(0) -> sts buf0 -> ldg(1)
    float4 bv0, bv1;
    bv0 = *(const float4*)(bbase);
    bv1 = *(const float4*)(bbase + 8 * DIM);
    {
        float r0[4] = {bv0.x, bv0.y, bv0.z, bv0.w};
        float r1[4] = {bv1.x, bv1.y, bv1.z, bv1.w};
#pragma unroll
        for (int j = 0; j < 4; j++) {
            sts_f32(sBt + j * ROWB,      f2tf_f(r0[j]));
            sts_f32(sBt + j * ROWB + 32, f2tf_f(r1[j]));
        }
    }
    bv0 = *(const float4*)(bbase + (size_t)16 * DIM);
    bv1 = *(const float4*)(bbase + (size_t)24 * DIM);

    for (int it = 0; it < NIT; ++it) {
        cp_wait<STAGES - 2>();
        __syncthreads();
        const int pf = it + STAGES - 1;
        if (pf < NIT) {
            const int ps = pf & (STAGES - 1);
            cp16(dA + ps * TILEB, asrc + (size_t)pf * 64);
            cp16(dA + ps * TILEB + 16, asrc + (size_t)pf * 64 + 16);
        }
        cp_commit();
        if (it + 1 < NIT) {
            const uint32_t dBt = sBt + ((it + 1) & 1) * TILEB;
            float r0[4] = {bv0.x, bv0.y, bv0.z, bv0.w};
            float r1[4] = {bv1.x, bv1.y, bv1.z, bv1.w};
#pragma unroll
            for (int j = 0; j < 4; j++) {
                sts_f32(dBt + j * ROWB,      f2tf_f(r0[j]));
                sts_f32(dBt + j * ROWB + 32, f2tf_f(r1[j]));
            }
            if (it + 2 < NIT) {
                bv0 = *(const float4*)(bbase + (size_t)(it + 2) * 16 * DIM);
                bv1 = *(const float4*)(bbase + (size_t)((it + 2) * 16 + 8) * DIM);
            }
        }
        const int s = it & (STAGES - 1);
        compute_iter<0>(sA0 + s * TILEB, sB0 + (it & 1) * TILEB, m0, n0, lane, acc);
    }

    const int rbase = lane >> 2, cbase = (lane & 3) * 2;
#pragma unroll
    for (int mi = 0; mi < 4; mi++) {
#pragma unroll
        for (int nj = 0; nj < 4; nj++) {
#pragma unroll
            for (int hrow = 0; hrow < 2; hrow++) {
                int rl = m0 + mi * 16 + rbase + hrow * 8;
                int d = col0 + n0 + nj * 8 + cbase;
                float v0 = acc[mi][nj][hrow * 2 + 0] + b2[e * DIM + d];
                float v1 = acc[mi][nj][hrow * 2 + 1] + b2[e * DIM + d + 1];
                float* dst = g_yo + (size_t)(e * CAP + row0 + rl) * DIM + d;
                *(float2*)dst = make_float2(v0, v1);
            }
        }
    }
}

// ---------------- combine ----------------
__global__ void combine_kernel(float* __restrict__ out) {
    int t = blockIdx.x;
    int d = threadIdx.x * 4;
    int s0 = g_pair_slot[2 * t + 0];
    int s1 = g_pair_slot[2 * t + 1];
    float w0 = g_pair_w[2 * t + 0];
    float w1v = g_pair_w[2 * t + 1];
    float4 r = make_float4(0.f, 0.f, 0.f, 0.f);
    if (s0 >= 0) {
        float4 a = *(const float4*)(g_yo + (size_t)s0 * DIM + d);
        r.x += w0 * a.x; r.y += w0 * a.y; r.z += w0 * a.z; r.w += w0 * a.w;
    }
    if (s1 >= 0) {
        float4 a = *(const float4*)(g_yo + (size_t)s1 * DIM + d);
        r.x += w1v * a.x; r.y += w1v * a.y; r.z += w1v * a.z; r.w += w1v * a.w;
    }
    *(float4*)(out + (size_t)t * DIM + d) = r;
}

// ---------------- launch ----------------
extern "C" void kernel_launch(void* const* d_in, const int* in_sizes, int n_in,
                              void* d_out, int out_size) {
    const float* x      = (const float*)d_in[0];
    const float* gate_w = (const float*)d_in[1];
    const float* gate_b = (const float*)d_in[2];
    const float* w1     = (const float*)d_in[3];
    const float* b1     = (const float*)d_in[4];
    const float* w2     = (const float*)d_in[5];
    const float* b2     = (const float*)d_in[6];
    float* out = (float*)d_out;

    static int configured = 0;
    if (!configured) {
        cudaFuncSetAttribute(gemm1_kernel, cudaFuncAttributeMaxDynamicSharedMemorySize, SMEMB1);
        cudaFuncSetAttribute(gemm2_kernel, cudaFuncAttributeMaxDynamicSharedMemorySize, SMEMB2);
        configured = 1;
    }

    float* xr; cudaGetSymbolAddress((void**)&xr, g_xr);

    gate_kernel<<<NTOK / 8, 256>>>(x, gate_w, gate_b);
    scan_kernel<<<1, 32>>>();
    roundx_kernel<<<NTOK * DIM / 4 / 256, 256>>>(x, xr);
    gemm1_kernel<<<dim3(FF / 128, CAP / 128, NEXP), 256, SMEMB1>>>(w1, b1);
    gemm2_kernel<<<dim3(DIM / 128, CAP / 128, NEXP), 256, SMEMB2>>>(w2, b2);
    combine_kernel<<<NTOK, 256>>>(out);
}

// round 13
// speedup vs baseline: 1.2627x; 1.2627x over previous
#include <cuda_runtime.h>
#include <math.h>
#include <stdint.h>

#define NTOK 4096
#define DIM  1024
#define FF   4096
#define NEXP 32
#define TOPK 2
#define CAP  512

__device__ float g_xr [(size_t)NTOK * DIM];        // 16 MB: x pre-rounded to tf32
__device__ float g_h  [(size_t)NEXP * CAP * FF];   // 256 MB: gelu(fc1), rounded, k-major
__device__ float g_yo [(size_t)NEXP * CAP * DIM];  // 64 MB
__device__ int   g_slot_token[NEXP * CAP];
__device__ int   g_pair_slot[NTOK * TOPK];
__device__ float g_pair_w[NTOK * TOPK];
__device__ int   g_topi[NTOK * TOPK];
__device__ int   g_nused[NEXP];

// ---------------- helpers ----------------
__device__ __forceinline__ uint32_t smem_u32(const void* p) {
    uint32_t a;
    asm("{ .reg .u64 t; cvta.to.shared.u64 t, %1; cvt.u32.u64 %0, t; }" : "=r"(a) : "l"(p));
    return a;
}
__device__ __forceinline__ void cp16(uint32_t d, const void* s) {
    asm volatile("cp.async.cg.shared.global [%0], [%1], 16;" :: "r"(d), "l"(s));
}
__device__ __forceinline__ void cp_commit() { asm volatile("cp.async.commit_group;"); }
template <int N>
__device__ __forceinline__ void cp_wait() { asm volatile("cp.async.wait_group %0;" :: "n"(N)); }

__device__ __forceinline__ void sts_f32(uint32_t addr, float v) {
    asm volatile("st.shared.f32 [%0], %1;" :: "r"(addr), "f"(v));
}
__device__ __forceinline__ void ldsm_x4(uint32_t& r0, uint32_t& r1, uint32_t& r2, uint32_t& r3,
                                        uint32_t addr) {
    asm volatile("ldmatrix.sync.aligned.m8n8.x4.shared.b16 {%0,%1,%2,%3}, [%4];"
                 : "=r"(r0), "=r"(r1), "=r"(r2), "=r"(r3) : "r"(addr));
}
__device__ __forceinline__ void ldsm_x2(uint32_t& r0, uint32_t& r1, uint32_t addr) {
    asm volatile("ldmatrix.sync.aligned.m8n8.x2.shared.b16 {%0,%1}, [%2];"
                 : "=r"(r0), "=r"(r1) : "r"(addr));
}
__device__ __forceinline__ uint32_t f2tf(uint32_t x) {
    uint32_t r;
    asm("cvt.rna.tf32.f32 %0, %1;" : "=r"(r) : "f"(__uint_as_float(x)));
    return r;
}
__device__ __forceinline__ float f2tf_f(float x) {
    uint32_t r;
    asm("cvt.rna.tf32.f32 %0, %1;" : "=r"(r) : "f"(x));
    return __uint_as_float(r);
}
__device__ __forceinline__ void mma_tf32(float* c, uint32_t a0, uint32_t a1, uint32_t a2,
                                         uint32_t a3, uint32_t b0, uint32_t b1) {
    asm volatile(
        "mma.sync.aligned.m16n8k8.row.col.f32.tf32.tf32.f32 "
        "{%0,%1,%2,%3}, {%4,%5,%6,%7}, {%8,%9}, {%0,%1,%2,%3};"
        : "+f"(c[0]), "+f"(c[1]), "+f"(c[2]), "+f"(c[3])
        : "r"(a0), "r"(a1), "r"(a2), "r"(a3), "r"(b0), "r"(b1));
}
__device__ __forceinline__ float gelu_tanh(float v) {
    float c = v + 0.044715f * v * v * v;
    return 0.5f * v * (1.0f + tanhf(0.7978845608028654f * c));
}

#define ROWB   80          // smem row stride: 64B (16 fp32 = K16) + 16B pad
#define TILEB  (128 * ROWB)
#define STAGES 4
#define SMEMB1 (2 * STAGES * TILEB + 512)         // gemm1: A+B 4-stage + tok
#define SMEMB2 (STAGES * TILEB + 2 * TILEB + 512) // gemm2: A 4-stage + B double buf

// ---------------- pre-round x: fp32 -> tf32(RNA) bits ----------------------
__global__ __launch_bounds__(256) void roundx_kernel(const float* __restrict__ src,
                                                     float* __restrict__ dst) {
    int i = blockIdx.x * 256 + threadIdx.x;
    const float4* s = (const float4*)src;
    float4* d = (float4*)dst;
    float4 v = s[i];
    d[i] = make_float4(f2tf_f(v.x), f2tf_f(v.y), f2tf_f(v.z), f2tf_f(v.w));
}

// ---------------- gating ----------------
__global__ void gate_kernel(const float* __restrict__ x, const float* __restrict__ gw,
                            const float* __restrict__ gb) {
    int warp = (blockIdx.x * blockDim.x + threadIdx.x) >> 5;
    int lane = threadIdx.x & 31;
    if (warp >= NTOK) return;
    const float4* xr = (const float4*)(x + (size_t)warp * DIM);
    float4 xv[8];
#pragma unroll
    for (int j = 0; j < 8; j++) xv[j] = xr[j * 32 + lane];
    float mylogit = 0.0f;
    for (int e = 0; e < NEXP; e++) {
        const float4* wr = (const float4*)(gw + (size_t)e * DIM);
        float s = 0.0f;
#pragma unroll
        for (int j = 0; j < 8; j++) {
            float4 wv = wr[j * 32 + lane];
            s += xv[j].x * wv.x + xv[j].y * wv.y + xv[j].z * wv.z + xv[j].w * wv.w;
        }
#pragma unroll
        for (int o = 16; o > 0; o >>= 1) s += __shfl_xor_sync(0xffffffffu, s, o);
        if (lane == e) mylogit = s + gb[e];
    }
    float m0 = mylogit; int i0 = lane;
#pragma unroll
    for (int o = 16; o > 0; o >>= 1) {
        float ov = __shfl_xor_sync(0xffffffffu, m0, o);
        int   oi = __shfl_xor_sync(0xffffffffu, i0, o);
        if (ov > m0 || (ov == m0 && oi < i0)) { m0 = ov; i0 = oi; }
    }
    float v2 = (lane == i0) ? -INFINITY : mylogit;
    float m1 = v2; int i1 = lane;
#pragma unroll
    for (int o = 16; o > 0; o >>= 1) {
        float ov = __shfl_xor_sync(0xffffffffu, m1, o);
        int   oi = __shfl_xor_sync(0xffffffffu, i1, o);
        if (ov > m1 || (ov == m1 && oi < i1)) { m1 = ov; i1 = oi; }
    }
    if (lane == 0) {
        float w0 = 1.0f / (1.0f + expf(m1 - m0));
        g_topi[warp * 2 + 0] = i0;
        g_topi[warp * 2 + 1] = i1;
        g_pair_w[warp * 2 + 0] = w0;
        g_pair_w[warp * 2 + 1] = 1.0f - w0;
    }
}

// ---------------- ordered capacity scan ----------------
__global__ void scan_kernel() {
    int lane = threadIdx.x;
    int cnt = 0;
    for (int base = 0; base < NTOK * TOPK; base += 32) {
        int v = g_topi[base + lane];
#pragma unroll
        for (int j = 0; j < 32; j++) {
            int ev = __shfl_sync(0xffffffffu, v, j);
            if (ev == lane) {
                int pos = cnt++;
                int i = base + j;
                if (pos < CAP) {
                    g_pair_slot[i] = lane * CAP + pos;
                    g_slot_token[lane * CAP + pos] = i >> 1;
                } else {
                    g_pair_slot[i] = -1;
                }
            }
        }
    }
    g_nused[lane] = min(cnt, CAP);
}

// ---------------- tf32 compute cores: warp tile 64x32, K=16 per iter -------
template <int CVTB>
__device__ __forceinline__ void compute_iter(uint32_t sA, uint32_t sB, int m0, int n0, int lane,
                                             float acc[4][4][4]) {
    uint32_t b[4][2][2];
    const uint32_t brow = (uint32_t)(n0 + (lane & 7)) * ROWB + (((lane >> 3) & 1) * 16);
#pragma unroll
    for (int nj = 0; nj < 4; nj++) {
        uint32_t ba = sB + brow + nj * 8 * ROWB;
        ldsm_x2(b[nj][0][0], b[nj][0][1], ba);        // k0-7
        ldsm_x2(b[nj][1][0], b[nj][1][1], ba + 32);   // k8-15
    }
    if (CVTB) {
#pragma unroll
        for (int nj = 0; nj < 4; nj++)
#pragma unroll
            for (int ks = 0; ks < 2; ks++) {
                b[nj][ks][0] = f2tf(b[nj][ks][0]);
                b[nj][ks][1] = f2tf(b[nj][ks][1]);
            }
    }
    const uint32_t arow = (uint32_t)(m0 + (lane & 15)) * ROWB + ((lane >> 4) * 16);
#pragma unroll
    for (int mi = 0; mi < 4; mi++) {
        uint32_t a0[4], a1[4];
        uint32_t aa = sA + arow + mi * 16 * ROWB;
        ldsm_x4(a0[0], a0[1], a0[2], a0[3], aa);        // k0-7
        ldsm_x4(a1[0], a1[1], a1[2], a1[3], aa + 32);   // k8-15
#pragma unroll
        for (int nj = 0; nj < 4; nj++)
            mma_tf32(acc[mi][nj], a0[0], a0[1], a0[2], a0[3], b[nj][0][0], b[nj][0][1]);
#pragma unroll
        for (int nj = 0; nj < 4; nj++)
            mma_tf32(acc[mi][nj], a1[0], a1[1], a1[2], a1[3], b[nj][1][0], b[nj][1][1]);
    }
}

__device__ __forceinline__ void fill_stage(uint32_t dA, uint32_t dB, const char* sa,
                                           const char* sb) {
    cp16(dA, sa); cp16(dA + 16, sa + 16);
    cp16(dB, sb); cp16(dB + 16, sb + 16);
}

// ---------------- GEMM1: h = gelu(gather(xr) @ w1^T + b1) ----------------
__global__ __launch_bounds__(256, 2) void gemm1_kernel(const float* __restrict__ w1,
                                                       const float* __restrict__ b1) {
    const int e = blockIdx.z;
    const int nu = g_nused[e];
    const int row0 = blockIdx.y * 128;
    if (row0 >= nu) return;
    const int col0 = blockIdx.x * 128;

    extern __shared__ __align__(16) char smem[];
    int* tok = (int*)(smem + 2 * STAGES * TILEB);
    const int tid = threadIdx.x;
    const int lane = tid & 31, wid = tid >> 5;
    const int m0 = (wid & 1) * 64, n0 = (wid >> 1) * 32;

    if (tid < 128) {
        int c = row0 + tid;
        tok[tid] = (c < nu) ? g_slot_token[e * CAP + c] : 0;
    }
    __syncthreads();

    const uint32_t sA0 = smem_u32(smem), sB0 = sA0 + STAGES * TILEB;
    const int r = tid >> 1, half = tid & 1;
    const char* asrc = (const char*)(g_xr + (size_t)tok[r] * DIM) + half * 32;
    const char* bsrc = (const char*)(w1 + ((size_t)e * FF + col0 + r) * DIM) + half * 32;
    const uint32_t dA = sA0 + r * ROWB + half * 32;
    const uint32_t dB = sB0 + r * ROWB + half * 32;

    float acc[4][4][4];
#pragma unroll
    for (int i = 0; i < 4; i++)
#pragma unroll
        for (int j = 0; j < 4; j++)
#pragma unroll
            for (int q = 0; q < 4; q++) acc[i][j][q] = 0.0f;

    const int NIT = DIM / 16;
#pragma unroll
    for (int s = 0; s < STAGES - 1; s++) {
        fill_stage(dA + s * TILEB, dB + s * TILEB, asrc + s * 64, bsrc + s * 64);
        cp_commit();
    }
    for (int it = 0; it < NIT; ++it) {
        cp_wait<STAGES - 2>();
        __syncthreads();
        const int pf = it + STAGES - 1;
        if (pf < NIT) {
            const int ps = pf & (STAGES - 1);
            fill_stage(dA + ps * TILEB, dB + ps * TILEB, asrc + (size_t)pf * 64,
                       bsrc + (size_t)pf * 64);
        }
        cp_commit();
        const int s = it & (STAGES - 1);
        compute_iter<1>(sA0 + s * TILEB, sB0 + s * TILEB, m0, n0, lane, acc);
    }

    // epilogue: bias + gelu, rounded to tf32 -> g_h (k-major for GEMM2)
    const int rbase = lane >> 2, cbase = (lane & 3) * 2;
#pragma unroll
    for (int mi = 0; mi < 4; mi++) {
#pragma unroll
        for (int nj = 0; nj < 4; nj++) {
#pragma unroll
            for (int hrow = 0; hrow < 2; hrow++) {
                int rl = m0 + mi * 16 + rbase + hrow * 8;
                int f = col0 + n0 + nj * 8 + cbase;
                float v0 = acc[mi][nj][hrow * 2 + 0] + b1[e * FF + f];
                float v1 = acc[mi][nj][hrow * 2 + 1] + b1[e * FF + f + 1];
                v0 = f2tf_f(gelu_tanh(v0)); v1 = f2tf_f(gelu_tanh(v1));
                float* hr = g_h + (size_t)(e * CAP + row0 + rl) * FF + f;
                *(float2*)hr = make_float2(v0, v1);
            }
        }
    }
}

// ---------------- GEMM2: yo = h @ w2[e]^(T in smem) + b2 -------------------
// A (g_h) via cp.async 4-stage; B (native w2) via LDG-prefetch + transposed
// st.shared (2-way-conflict mapping) into a double-buffered [n][k] tile.
__global__ __launch_bounds__(256, 2) void gemm2_kernel(const float* __restrict__ w2,
                                                       const float* __restrict__ b2) {
    const int e = blockIdx.z;
    const int nu = g_nused[e];
    const int row0 = blockIdx.y * 128;
    if (row0 >= nu) return;
    const int col0 = blockIdx.x * 128;

    extern __shared__ __align__(16) char smem[];
    const int tid = threadIdx.x;
    const int lane = tid & 31, wid = tid >> 5;
    const int m0 = (wid & 1) * 64, n0 = (wid >> 1) * 32;

    const uint32_t sA0 = smem_u32(smem);
    const uint32_t sB0 = sA0 + STAGES * TILEB;     // two B buffers follow A stages
    const int r = tid >> 1, half = tid & 1;
    const char* asrc = (const char*)(g_h + (size_t)(e * CAP + row0 + r) * FF) + half * 32;
    const uint32_t dA = sA0 + r * ROWB + half * 32;

    // B transpose-fill: k = tid>>4 (0..15), n = (lane&15) + 16j (j=0..7)
    const int bk = tid >> 4;            // k row within the 16-k chunk
    const int bl = tid & 15;            // n base
    const float* bbase = w2 + (size_t)e * FF * DIM + (size_t)bk * DIM + col0 + bl;
    const uint32_t sBt = sB0 + (uint32_t)bl * ROWB + bk * 4;   // + j*16*ROWB per j

    float acc[4][4][4];
#pragma unroll
    for (int i = 0; i < 4; i++)
#pragma unroll
        for (int j = 0; j < 4; j++)
#pragma unroll
            for (int q = 0; q < 4; q++) acc[i][j][q] = 0.0f;

    const int NIT = FF / 16;

    // A prologue (stages 0..2)
#pragma unroll
    for (int s = 0; s < STAGES - 1; s++) {
        cp16(dA + s * TILEB, asrc + s * 64);
        cp16(dA + s * TILEB + 16, asrc + s * 64 + 16);
        cp_commit();
    }
    // B prologue: ldg(it=0) -> sts buf0 -> ldg(it=1)
    float bw[8];
#pragma unroll
    for (int j = 0; j < 8; j++) bw[j] = bbase[16 * j];
#pragma unroll
    for (int j = 0; j < 8; j++) sts_f32(sBt + (uint32_t)j * (16 * ROWB), f2tf_f(bw[j]));
#pragma unroll
    for (int j = 0; j < 8; j++) bw[j] = bbase[(size_t)16 * DIM + 16 * j];

    for (int it = 0; it < NIT; ++it) {
        cp_wait<STAGES - 2>();
        __syncthreads();
        const int pf = it + STAGES - 1;
        if (pf < NIT) {
            const int ps = pf & (STAGES - 1);
            cp16(dA + ps * TILEB, asrc + (size_t)pf * 64);
            cp16(dA + ps * TILEB + 16, asrc + (size_t)pf * 64 + 16);
        }
        cp_commit();
        if (it + 1 < NIT) {
            const uint32_t dBt = sBt + ((it + 1) & 1) * TILEB;
#pragma unroll
            for (int j = 0; j < 8; j++) sts_f32(dBt + (uint32_t)j * (16 * ROWB), f2tf_f(bw[j]));
            if (it + 2 < NIT) {
                const float* src = bbase + (size_t)(it + 2) * 16 * DIM;
#pragma unroll
                for (int j = 0; j < 8; j++) bw[j] = src[16 * j];
            }
        }
        const int s = it & (STAGES - 1);
        compute_iter<0>(sA0 + s * TILEB, sB0 + (it & 1) * TILEB, m0, n0, lane, acc);
    }

    const int rbase = lane >> 2, cbase = (lane & 3) * 2;
#pragma unroll
    for (int mi = 0; mi < 4; mi++) {
#pragma unroll
        for (int nj = 0; nj < 4; nj++) {
#pragma unroll
            for (int hrow = 0; hrow < 2; hrow++) {
                int rl = m0 + mi * 16 + rbase + hrow * 8;
                int d = col0 + n0 + nj * 8 + cbase;
                float v0 = acc[mi][nj][hrow * 2 + 0] + b2[e * DIM + d];
                float v1 = acc[mi][nj][hrow * 2 + 1] + b2[e * DIM + d + 1];
                float* dst = g_yo + (size_t)(e * CAP + row0 + rl) * DIM + d;
                *(float2*)dst = make_float2(v0, v1);
            }
        }
    }
}

// ---------------- combine ----------------
__global__ void combine_kernel(float* __restrict__ out) {
    int t = blockIdx.x;
    int d = threadIdx.x * 4;
    int s0 = g_pair_slot[2 * t + 0];
    int s1 = g_pair_slot[2 * t + 1];
    float w0 = g_pair_w[2 * t + 0];
    float w1v = g_pair_w[2 * t + 1];
    float4 r = make_float4(0.f, 0.f, 0.f, 0.f);
    if (s0 >= 0) {
        float4 a = *(const float4*)(g_yo + (size_t)s0 * DIM + d);
        r.x += w0 * a.x; r.y += w0 * a.y; r.z += w0 * a.z; r.w += w0 * a.w;
    }
    if (s1 >= 0) {
        float4 a = *(const float4*)(g_yo + (size_t)s1 * DIM + d);
        r.x += w1v * a.x; r.y += w1v * a.y; r.z += w1v * a.z; r.w += w1v * a.w;
    }
    *(float4*)(out + (size_t)t * DIM + d) = r;
}

// ---------------- launch ----------------
extern "C" void kernel_launch(void* const* d_in, const int* in_sizes, int n_in,
                              void* d_out, int out_size) {
    const float* x      = (const float*)d_in[0];
    const float* gate_w = (const float*)d_in[1];
    const float* gate_b = (const float*)d_in[2];
    const float* w1     = (const float*)d_in[3];
    const float* b1     = (const float*)d_in[4];
    const float* w2     = (const float*)d_in[5];
    const float* b2     = (const float*)d_in[6];
    float* out = (float*)d_out;

    static int configured = 0;
    if (!configured) {
        cudaFuncSetAttribute(gemm1_kernel, cudaFuncAttributeMaxDynamicSharedMemorySize, SMEMB1);
        cudaFuncSetAttribute(gemm2_kernel, cudaFuncAttributeMaxDynamicSharedMemorySize, SMEMB2);
        configured = 1;
    }

    float* xr; cudaGetSymbolAddress((void**)&xr, g_xr);

    gate_kernel<<<NTOK / 8, 256>>>(x, gate_w, gate_b);
    scan_kernel<<<1, 32>>>();
    roundx_kernel<<<NTOK * DIM / 4 / 256, 256>>>(x, xr);
    gemm1_kernel<<<dim3(FF / 128, CAP / 128, NEXP), 256, SMEMB1>>>(w1, b1);
    gemm2_kernel<<<dim3(DIM / 128, CAP / 128, NEXP), 256, SMEMB2>>>(w2, b2);
    combine_kernel<<<NTOK, 256>>>(out);
}